// round 8
// baseline (speedup 1.0000x reference)
#include <cuda_runtime.h>

// SpikeLayer LIF scan: x [B=64, T=8, C=256, H=32, W=32] f32 -> spikes, same shape.
// mem = mem*0.25 + x; spike = (mem - 0.5) > 0; mem = (1-spike)*mem.
//
// FINAL (converged at HBM ceiling): one thread = 4 neurons (one float4) across
// all 8 timesteps; recurrence entirely in registers; front-batched MLP=8
// fully-coalesced LDG.128; default cache ops; flat 2D grid (y = batch);
// 512-thread CTAs; all 32-bit index math.
//
// Evidence of convergence (R1-R7): six variants (cache hints, persistent
// grid-stride, MLP=16, CTA 256/512) all land at 6.76-6.80 TB/s = 85% of spec
// HBM with traffic pinned exactly at the 1 GiB floor (512 MiB in + 512 MiB
// f32 out, incompressible). Compute pipes <6%, issue ~12%, occupancy
// non-binding. Remaining gap to spec is DRAM refresh + read/write bus
// turnaround on a 50/50 mixed stream - not addressable from the kernel.

#define LIF_T 8
#define VTH 0.5f
#define DECAY 0.25f
#define CHW4 65536u                  // C*H*W/4 float4 vectors per (b,t) slice
#define BSTRIDE (CHW4 * 8u)          // float4 vectors per batch sample
#define TPB 512u

__global__ __launch_bounds__(TPB) void lif_scan_kernel(
    const float4* __restrict__ x, float4* __restrict__ out)
{
    unsigned n    = blockIdx.x * TPB + threadIdx.x;    // [0, CHW4)
    unsigned base = blockIdx.y * BSTRIDE + n;

    float4 v[LIF_T];
    // Front-batched independent loads: MLP = 8 LDG.128
    #pragma unroll
    for (int t = 0; t < LIF_T; t++)
        v[t] = x[base + (unsigned)t * CHW4];

    float mx = 0.f, my = 0.f, mz = 0.f, mw = 0.f;
    #pragma unroll
    for (int t = 0; t < LIF_T; t++) {
        mx = fmaf(mx, DECAY, v[t].x);
        my = fmaf(my, DECAY, v[t].y);
        mz = fmaf(mz, DECAY, v[t].z);
        mw = fmaf(mw, DECAY, v[t].w);
        float sx = (mx > VTH) ? 1.f : 0.f;
        float sy = (my > VTH) ? 1.f : 0.f;
        float sz = (mz > VTH) ? 1.f : 0.f;
        float sw = (mw > VTH) ? 1.f : 0.f;
        // hard reset where spiked
        mx = (sx != 0.f) ? 0.f : mx;
        my = (sy != 0.f) ? 0.f : my;
        mz = (sz != 0.f) ? 0.f : mz;
        mw = (sw != 0.f) ? 0.f : mw;
        v[t].x = sx; v[t].y = sy; v[t].z = sz; v[t].w = sw;
    }

    #pragma unroll
    for (int t = 0; t < LIF_T; t++)
        out[base + (unsigned)t * CHW4] = v[t];
}

extern "C" void kernel_launch(void* const* d_in, const int* in_sizes, int n_in,
                              void* d_out, int out_size)
{
    const float4* x = (const float4*)d_in[0];
    float4* out = (float4*)d_out;

    unsigned total   = (unsigned)in_sizes[0];          // B*T*C*H*W
    unsigned batches = total / (LIF_T * CHW4 * 4u);    // = 64 for bench shape

    dim3 grid(CHW4 / TPB, batches, 1);                 // (128, 64) = 8192 CTAs
    lif_scan_kernel<<<grid, TPB>>>(x, out);
}

// round 9
// speedup vs baseline: 1.0002x; 1.0002x over previous
#include <cuda_runtime.h>

// SpikeLayer LIF scan: x [B=64, T=8, C=256, H=32, W=32] f32 -> spikes, same shape.
// mem = mem*0.25 + x; spike = (mem - 0.5) > 0; mem = (1-spike)*mem.
//
// FINAL (converged at HBM ceiling): one thread = 4 neurons (one float4) across
// all 8 timesteps; recurrence entirely in registers; front-batched MLP=8
// fully-coalesced LDG.128; default cache ops; flat 2D grid (y = batch);
// 512-thread CTAs; all 32-bit index math.
//
// Convergence evidence (R1-R8): all well-formed variants (cache hints,
// persistent grid-stride, MLP=16, CTA 256/512) land at 6.76-6.80 TB/s = 85%
// of spec HBM with traffic pinned exactly at the 1 GiB floor (512 MiB in +
// 512 MiB f32 out, incompressible). Compute pipes <6%, issue ~12%, occupancy
// non-binding. Remaining gap to spec is DRAM refresh + read/write bus
// turnaround on a 50/50 mixed stream - not addressable from the kernel.

#define LIF_T 8
#define VTH 0.5f
#define DECAY 0.25f
#define CHW4 65536u                  // C*H*W/4 float4 vectors per (b,t) slice
#define BSTRIDE (CHW4 * 8u)          // float4 vectors per batch sample
#define TPB 512u

__global__ __launch_bounds__(TPB) void lif_scan_kernel(
    const float4* __restrict__ x, float4* __restrict__ out)
{
    unsigned n    = blockIdx.x * TPB + threadIdx.x;    // [0, CHW4)
    unsigned base = blockIdx.y * BSTRIDE + n;

    float4 v[LIF_T];
    // Front-batched independent loads: MLP = 8 LDG.128
    #pragma unroll
    for (int t = 0; t < LIF_T; t++)
        v[t] = x[base + (unsigned)t * CHW4];

    float mx = 0.f, my = 0.f, mz = 0.f, mw = 0.f;
    #pragma unroll
    for (int t = 0; t < LIF_T; t++) {
        mx = fmaf(mx, DECAY, v[t].x);
        my = fmaf(my, DECAY, v[t].y);
        mz = fmaf(mz, DECAY, v[t].z);
        mw = fmaf(mw, DECAY, v[t].w);
        float sx = (mx > VTH) ? 1.f : 0.f;
        float sy = (my > VTH) ? 1.f : 0.f;
        float sz = (mz > VTH) ? 1.f : 0.f;
        float sw = (mw > VTH) ? 1.f : 0.f;
        // hard reset where spiked
        mx = (sx != 0.f) ? 0.f : mx;
        my = (sy != 0.f) ? 0.f : my;
        mz = (sz != 0.f) ? 0.f : mz;
        mw = (sw != 0.f) ? 0.f : mw;
        v[t].x = sx; v[t].y = sy; v[t].z = sz; v[t].w = sw;
    }

    #pragma unroll
    for (int t = 0; t < LIF_T; t++)
        out[base + (unsigned)t * CHW4] = v[t];
}

extern "C" void kernel_launch(void* const* d_in, const int* in_sizes, int n_in,
                              void* d_out, int out_size)
{
    const float4* x = (const float4*)d_in[0];
    float4* out = (float4*)d_out;

    unsigned total   = (unsigned)in_sizes[0];          // B*T*C*H*W
    unsigned batches = total / (LIF_T * CHW4 * 4u);    // = 64 for bench shape

    dim3 grid(CHW4 / TPB, batches, 1);                 // (128, 64) = 8192 CTAs
    lif_scan_kernel<<<grid, TPB>>>(x, out);
}